// round 2
// baseline (speedup 1.0000x reference)
#include <cuda_runtime.h>
#include <math.h>

#define N_NODES   200000
#define N_EDGES   6400000
#define HIDF      128
#define N_GRAPHS  64

// ---------------- scratch (device globals: allocation-free rule) ----------------
// NOTE: these symbols must ONLY be referenced from device code. Passing them as
// kernel arguments from host code passes the host-side shadow address (silently
// wrong on GB300 due to ATS) — that was the Round-1 bug.
__device__ float g_dinv[N_NODES];              // deg -> rsqrt(deg)
__device__ float g_coef[N_EDGES];              // dinv[s]*ew*dinv[d], reused by both layers
__device__ float g_H[(size_t)N_NODES * HIDF];  // x@W result
__device__ float g_B[(size_t)N_NODES * HIDF];  // aggregation output
__device__ float g_sums[N_GRAPHS * HIDF];
__device__ float g_counts[N_GRAPHS];

// ---------------- degree / normalization ----------------
__global__ void init_deg_kernel(int n) {
    int i = blockIdx.x * blockDim.x + threadIdx.x;
    if (i < n) g_dinv[i] = 1.0f;   // self-loop weight
}

__global__ void deg_add_kernel(const int* __restrict__ dst,
                               const float* __restrict__ ew, int ne) {
    int e = blockIdx.x * blockDim.x + threadIdx.x;
    if (e < ne) atomicAdd(&g_dinv[dst[e]], ew[e]);
}

__global__ void dinv_kernel(int n) {
    int i = blockIdx.x * blockDim.x + threadIdx.x;
    if (i < n) {
        float d = g_dinv[i];
        g_dinv[i] = (d > 0.0f) ? rsqrtf(d) : 0.0f;
    }
}

__global__ void coef_kernel(const int* __restrict__ src, const int* __restrict__ dst,
                            const float* __restrict__ ew, int ne) {
    int e = blockIdx.x * blockDim.x + threadIdx.x;
    if (e < ne) g_coef[e] = g_dinv[src[e]] * ew[e] * g_dinv[dst[e]];
}

// ---------------- SGEMM: g_H[n,128] = act(X[n,128]) @ W[128,128] ----------------
// src_sel = 0: X = Xext (raw). src_sel = 1: X = g_B with ELU applied.
// 256 threads = 8 warps; each warp computes 4 rows; lane owns 4 output cols.
__global__ void gemm128_kernel(const float* __restrict__ Xext,
                               const float* __restrict__ W,
                               int n, int src_sel) {
    __shared__ float sW[32][HIDF];    // 16KB K-chunk of W
    __shared__ float sX[8][4][32];    // per-warp staged x chunk

    const float* X = src_sel ? (const float*)g_B : Xext;

    const int t = threadIdx.x;
    const int w = t >> 5, l = t & 31;
    const int row0 = (blockIdx.x * 8 + w) * 4;

    float acc[4][4];
#pragma unroll
    for (int r = 0; r < 4; ++r)
#pragma unroll
        for (int j = 0; j < 4; ++j) acc[r][j] = 0.0f;

    for (int c = 0; c < 4; ++c) {
        // stage W rows [32c, 32c+32)
        const float4* Wv = (const float4*)(W + c * 32 * HIDF);
        float4* sWv = (float4*)&sW[0][0];
#pragma unroll
        for (int i = 0; i < 4; ++i) sWv[t + 256 * i] = Wv[t + 256 * i];
        // stage this warp's 4 x-rows, k-chunk [32c, 32c+32)
#pragma unroll
        for (int r = 0; r < 4; ++r) {
            int row = row0 + r;
            float v = 0.0f;
            if (row < n) v = X[(size_t)row * HIDF + c * 32 + l];
            if (src_sel) v = (v > 0.0f) ? v : expm1f(v);   // ELU
            sX[w][r][l] = v;
        }
        __syncthreads();
#pragma unroll
        for (int k = 0; k < 32; ++k) {
            float4 wv = *(const float4*)&sW[k][l * 4];
#pragma unroll
            for (int r = 0; r < 4; ++r) {
                float xv = sX[w][r][k];
                acc[r][0] += xv * wv.x;
                acc[r][1] += xv * wv.y;
                acc[r][2] += xv * wv.z;
                acc[r][3] += xv * wv.w;
            }
        }
        __syncthreads();
    }
#pragma unroll
    for (int r = 0; r < 4; ++r) {
        int row = row0 + r;
        if (row < n)
            *(float4*)&g_H[(size_t)row * HIDF + l * 4] =
                make_float4(acc[r][0], acc[r][1], acc[r][2], acc[r][3]);
    }
}

// ---------------- self-loop init: B[i,:] = dinv[i]^2 * H[i,:] + bias ----------------
__global__ void self_init_kernel(const float* __restrict__ bias, int n) {
    int idx = blockIdx.x * blockDim.x + threadIdx.x;   // over n*32 float4 slots
    if (idx >= n * 32) return;
    int i = idx >> 5, c4 = idx & 31;
    float di = g_dinv[i];
    float s = di * di;
    float4 h = ((const float4*)g_H)[idx];
    float4 b = ((const float4*)bias)[c4];
    ((float4*)g_B)[idx] = make_float4(s * h.x + b.x, s * h.y + b.y,
                                      s * h.z + b.z, s * h.w + b.w);
}

// ---------------- edge aggregation: B[dst] += coef[e] * H[src] ----------------
// one warp per edge; lane handles 4 contiguous cols (coalesced 512B gather)
__global__ void agg_edges_kernel(const int* __restrict__ src, const int* __restrict__ dst,
                                 int ne) {
    int e = (blockIdx.x * blockDim.x + threadIdx.x) >> 5;
    int l = threadIdx.x & 31;
    if (e >= ne) return;
    int s = __ldg(src + e);
    int d = __ldg(dst + e);
    float c = g_coef[e];
    float4 hv = *(const float4*)(g_H + (size_t)s * HIDF + l * 4);
    float* bp = g_B + (size_t)d * HIDF + l * 4;
    atomicAdd(bp + 0, c * hv.x);
    atomicAdd(bp + 1, c * hv.y);
    atomicAdd(bp + 2, c * hv.z);
    atomicAdd(bp + 3, c * hv.w);
}

// ---------------- pooling ----------------
__global__ void zero_pool_kernel() {
    int t = blockIdx.x * blockDim.x + threadIdx.x;
    if (t < N_GRAPHS * HIDF) g_sums[t] = 0.0f;
    if (t < N_GRAPHS) g_counts[t] = 0.0f;
}

// block handles 256 contiguous nodes; batch is sorted, so accumulate runs and
// flush to global atomics only at graph boundaries.
__global__ void pool_kernel(const int* __restrict__ batch, int n) {
    __shared__ int sb[256];
    __shared__ int scnt[N_GRAPHS];
    int t = threadIdx.x;
    int base = blockIdx.x * 256;
    if (t < N_GRAPHS) scnt[t] = 0;
    __syncthreads();
    int node = base + t;
    int g = -1;
    if (node < n) {
        g = batch[node];
        atomicAdd(&scnt[g], 1);
    }
    sb[t] = g;
    __syncthreads();
    if (t < N_GRAPHS && scnt[t] > 0) atomicAdd(&g_counts[t], (float)scnt[t]);

    int w = t >> 5, l = t & 31;
    int r0 = w * 32;
    float4 acc = make_float4(0.f, 0.f, 0.f, 0.f);
    int curg = -1;
    for (int r = 0; r < 32; ++r) {
        int gg = sb[r0 + r];
        if (gg < 0) break;
        if (gg != curg) {
            if (curg >= 0) {
                float* sp = g_sums + curg * HIDF + l * 4;
                atomicAdd(sp + 0, acc.x); atomicAdd(sp + 1, acc.y);
                atomicAdd(sp + 2, acc.z); atomicAdd(sp + 3, acc.w);
                acc = make_float4(0.f, 0.f, 0.f, 0.f);
            }
            curg = gg;
        }
        float4 v = *(const float4*)(g_B + (size_t)(base + r0 + r) * HIDF + l * 4);
        acc.x += v.x; acc.y += v.y; acc.z += v.z; acc.w += v.w;
    }
    if (curg >= 0) {
        float* sp = g_sums + curg * HIDF + l * 4;
        atomicAdd(sp + 0, acc.x); atomicAdd(sp + 1, acc.y);
        atomicAdd(sp + 2, acc.z); atomicAdd(sp + 3, acc.w);
    }
}

// ---------------- final FC: out[g] = (sums[g]/max(cnt,1)) . Wfc + bfc ----------------
__global__ void fc_kernel(const float* __restrict__ Wfc, const float* __restrict__ bfc,
                          float* __restrict__ out) {
    int g = blockIdx.x, t = threadIdx.x;   // 128 threads
    float cnt = g_counts[g];
    cnt = (cnt > 1.0f) ? cnt : 1.0f;
    float v = g_sums[g * HIDF + t] * (1.0f / cnt) * Wfc[t];
#pragma unroll
    for (int o = 16; o; o >>= 1) v += __shfl_down_sync(0xffffffffu, v, o);
    __shared__ float sr[4];
    if ((t & 31) == 0) sr[t >> 5] = v;
    __syncthreads();
    if (t == 0) out[g] = sr[0] + sr[1] + sr[2] + sr[3] + bfc[0];
}

// ---------------- launch ----------------
extern "C" void kernel_launch(void* const* d_in, const int* in_sizes, int n_in,
                              void* d_out, int out_size) {
    const float* x   = (const float*)d_in[0];
    const int*   ei  = (const int*)  d_in[1];
    const float* ew  = (const float*)d_in[2];
    const int*   bat = (const int*)  d_in[3];
    const float* W1  = (const float*)d_in[4];
    // b1 = d_in[5]
    const float* W2  = (const float*)d_in[6];
    // b2 = d_in[7]
    const float* Wfc = (const float*)d_in[8];
    const float* bfc = (const float*)d_in[9];
    const float* b1  = (const float*)d_in[5];
    const float* b2  = (const float*)d_in[7];
    float* out = (float*)d_out;

    const int n  = in_sizes[3];   // nodes (batch vector)
    const int ne = in_sizes[2];   // edges (edge_weight vector)
    const int* src = ei;
    const int* dst = ei + ne;

    // normalization coefficients (shared by both layers)
    init_deg_kernel<<<(n + 255) / 256, 256>>>(n);
    deg_add_kernel<<<(ne + 255) / 256, 256>>>(dst, ew, ne);
    dinv_kernel<<<(n + 255) / 256, 256>>>(n);
    coef_kernel<<<(ne + 255) / 256, 256>>>(src, dst, ew, ne);

    const int gemm_blocks = (n + 31) / 32;
    const int vec_blocks  = (n * 32 + 255) / 256;
    const int agg_blocks  = (ne + 7) / 8;

    // layer 1: H = x@W1 ; B = dinv^2*H + b1 ; B += scatter(coef * H[src])
    gemm128_kernel<<<gemm_blocks, 256>>>(x, W1, n, 0);
    self_init_kernel<<<vec_blocks, 256>>>(b1, n);
    agg_edges_kernel<<<agg_blocks, 256>>>(src, dst, ne);

    // layer 2: H = elu(B)@W2 ; B = dinv^2*H + b2 ; B += scatter(coef * H[src])
    gemm128_kernel<<<gemm_blocks, 256>>>(x /*unused*/, W2, n, 1);
    self_init_kernel<<<vec_blocks, 256>>>(b2, n);
    agg_edges_kernel<<<agg_blocks, 256>>>(src, dst, ne);

    // mean pool + FC
    zero_pool_kernel<<<(N_GRAPHS * HIDF + 255) / 256, 256>>>();
    pool_kernel<<<(n + 255) / 256, 256>>>(bat, n);
    fc_kernel<<<N_GRAPHS, HIDF>>>(Wfc, bfc, out);
}

// round 3
// speedup vs baseline: 2.7688x; 2.7688x over previous
#include <cuda_runtime.h>
#include <math.h>

#define N_NODES   200000
#define N_EDGES   6400000
#define HIDF      128
#define N_GRAPHS  64

// ---------------- scratch (device globals; referenced from device code ONLY) ----
__device__ float g_dinv[N_NODES];                 // weighted deg -> rsqrt(deg)
__device__ int   g_cnt[N_NODES];                  // in-degree (edge count)
__device__ int   g_fill[N_NODES];                 // scatter cursor
__device__ int   g_rowptr[N_NODES + 1];           // CSR row pointers (by dst)
__device__ int2  g_edge[N_EDGES];                 // {src, coef bits} sorted by dst
__device__ float g_H[(size_t)N_NODES * HIDF];     // X@W
__device__ float g_B[(size_t)N_NODES * HIDF];     // layer output
__device__ float g_sums[N_GRAPHS * HIDF];
__device__ float g_counts[N_GRAPHS];

// ---------------- preprocess: degrees + counts ----------------
__global__ void zero_meta_kernel(int n) {
    int i = blockIdx.x * blockDim.x + threadIdx.x;
    if (i < n) {
        g_dinv[i] = 1.0f;   // self-loop weight seed
        g_cnt[i]  = 0;
        g_fill[i] = 0;
    }
}

__global__ void hist_kernel(const int* __restrict__ dst,
                            const float* __restrict__ ew, int ne) {
    int e = blockIdx.x * blockDim.x + threadIdx.x;
    if (e < ne) {
        int d = dst[e];
        atomicAdd(&g_dinv[d], ew[e]);
        atomicAdd(&g_cnt[d], 1);
    }
}

__global__ void dinv_kernel(int n) {
    int i = blockIdx.x * blockDim.x + threadIdx.x;
    if (i < n) {
        float d = g_dinv[i];
        g_dinv[i] = (d > 0.0f) ? rsqrtf(d) : 0.0f;
    }
}

// single-block exclusive scan of g_cnt -> g_rowptr (n up to ~1M fine)
__global__ void scan_kernel(int n) {
    __shared__ int warp_sums[32];
    const int t = threadIdx.x;                 // 1024 threads
    const int chunk = (n + 1023) >> 10;
    const int beg = t * chunk;
    const int end = min(beg + chunk, n);

    int sum = 0;
    for (int i = beg; i < end; ++i) sum += g_cnt[i];

    // inclusive scan of per-thread sums
    int v = sum;
#pragma unroll
    for (int o = 1; o < 32; o <<= 1) {
        int u = __shfl_up_sync(0xffffffffu, v, o);
        if ((t & 31) >= o) v += u;
    }
    if ((t & 31) == 31) warp_sums[t >> 5] = v;
    __syncthreads();
    if (t < 32) {
        int w = warp_sums[t];
#pragma unroll
        for (int o = 1; o < 32; o <<= 1) {
            int u = __shfl_up_sync(0xffffffffu, w, o);
            if (t >= o) w += u;
        }
        warp_sums[t] = w;
    }
    __syncthreads();

    int excl = v - sum + ((t >= 32) ? warp_sums[(t >> 5) - 1] : 0);
    int running = excl;
    for (int i = beg; i < end; ++i) {
        g_rowptr[i] = running;
        running += g_cnt[i];
    }
    if (beg < n && end == n) g_rowptr[n] = running;
}

// scatter edges into dst-sorted CSR, coef computed inline
__global__ void scatter_kernel(const int* __restrict__ src, const int* __restrict__ dst,
                               const float* __restrict__ ew, int ne) {
    int e = blockIdx.x * blockDim.x + threadIdx.x;
    if (e >= ne) return;
    int s = src[e], d = dst[e];
    float c = g_dinv[s] * ew[e] * g_dinv[d];
    int pos = g_rowptr[d] + atomicAdd(&g_fill[d], 1);
    g_edge[pos] = make_int2(s, __float_as_int(c));
}

// ---------------- SGEMM: g_H[n,128] = act(X[n,128]) @ W[128,128] ----------------
// src_sel=0: X=Xext raw.  src_sel=1: X=g_B with ELU.
// 256 threads = 8 warps; warp computes 8 rows; lane owns 4 output cols.
__global__ void gemm128_kernel(const float* __restrict__ Xext,
                               const float* __restrict__ W,
                               int n, int src_sel) {
    __shared__ float sW[32][HIDF];     // 16KB K-chunk of W
    __shared__ float sX[8][8][32];     // 8KB per-warp staged x rows

    const float* X = src_sel ? (const float*)g_B : Xext;

    const int t = threadIdx.x;
    const int w = t >> 5, l = t & 31;
    const int row0 = (blockIdx.x * 8 + w) * 8;

    float acc[8][4];
#pragma unroll
    for (int r = 0; r < 8; ++r)
#pragma unroll
        for (int j = 0; j < 4; ++j) acc[r][j] = 0.0f;

    for (int c = 0; c < 4; ++c) {
        const float4* Wv = (const float4*)(W + c * 32 * HIDF);
        float4* sWv = (float4*)&sW[0][0];
#pragma unroll
        for (int i = 0; i < 4; ++i) sWv[t + 256 * i] = Wv[t + 256 * i];
#pragma unroll
        for (int r = 0; r < 8; ++r) {
            int row = row0 + r;
            float v = 0.0f;
            if (row < n) v = X[(size_t)row * HIDF + c * 32 + l];
            if (src_sel) v = (v > 0.0f) ? v : expm1f(v);   // ELU
            sX[w][r][l] = v;
        }
        __syncthreads();
#pragma unroll
        for (int k = 0; k < 32; ++k) {
            float4 wv = *(const float4*)&sW[k][l * 4];
#pragma unroll
            for (int r = 0; r < 8; ++r) {
                float xv = sX[w][r][k];
                acc[r][0] += xv * wv.x;
                acc[r][1] += xv * wv.y;
                acc[r][2] += xv * wv.z;
                acc[r][3] += xv * wv.w;
            }
        }
        __syncthreads();
    }
#pragma unroll
    for (int r = 0; r < 8; ++r) {
        int row = row0 + r;
        if (row < n)
            *(float4*)&g_H[(size_t)row * HIDF + l * 4] =
                make_float4(acc[r][0], acc[r][1], acc[r][2], acc[r][3]);
    }
}

// ---------------- CSR aggregation (atomic-free), self-loop + bias fused ---------
// one warp per dst node: B[d] = dinv[d]^2*H[d] + bias + sum_e coef*H[src]
__global__ void agg_csr_kernel(const float* __restrict__ bias, int n) {
    int node = (blockIdx.x * blockDim.x + threadIdx.x) >> 5;
    int l = threadIdx.x & 31;
    if (node >= n) return;

    int beg = g_rowptr[node];
    int end = g_rowptr[node + 1];

    float di = g_dinv[node];
    float s = di * di;
    float4 h = *(const float4*)(g_H + (size_t)node * HIDF + l * 4);
    float4 b = ((const float4*)bias)[l];
    float4 acc = make_float4(s * h.x + b.x, s * h.y + b.y,
                             s * h.z + b.z, s * h.w + b.w);

    for (int e = beg; e < end; ++e) {
        int2 ed = g_edge[e];
        float c = __int_as_float(ed.y);
        float4 hv = *(const float4*)(g_H + (size_t)ed.x * HIDF + l * 4);
        acc.x += c * hv.x;
        acc.y += c * hv.y;
        acc.z += c * hv.z;
        acc.w += c * hv.w;
    }
    *(float4*)(g_B + (size_t)node * HIDF + l * 4) = acc;
}

// ---------------- pooling ----------------
__global__ void zero_pool_kernel() {
    int t = blockIdx.x * blockDim.x + threadIdx.x;
    if (t < N_GRAPHS * HIDF) g_sums[t] = 0.0f;
    if (t < N_GRAPHS) g_counts[t] = 0.0f;
}

__global__ void pool_kernel(const int* __restrict__ batch, int n) {
    __shared__ int sb[256];
    __shared__ int scnt[N_GRAPHS];
    int t = threadIdx.x;
    int base = blockIdx.x * 256;
    if (t < N_GRAPHS) scnt[t] = 0;
    __syncthreads();
    int node = base + t;
    int g = -1;
    if (node < n) {
        g = batch[node];
        atomicAdd(&scnt[g], 1);
    }
    sb[t] = g;
    __syncthreads();
    if (t < N_GRAPHS && scnt[t] > 0) atomicAdd(&g_counts[t], (float)scnt[t]);

    int w = t >> 5, l = t & 31;
    int r0 = w * 32;
    float4 acc = make_float4(0.f, 0.f, 0.f, 0.f);
    int curg = -1;
    for (int r = 0; r < 32; ++r) {
        int gg = sb[r0 + r];
        if (gg < 0) break;
        if (gg != curg) {
            if (curg >= 0) {
                float* sp = g_sums + curg * HIDF + l * 4;
                atomicAdd(sp + 0, acc.x); atomicAdd(sp + 1, acc.y);
                atomicAdd(sp + 2, acc.z); atomicAdd(sp + 3, acc.w);
                acc = make_float4(0.f, 0.f, 0.f, 0.f);
            }
            curg = gg;
        }
        float4 v = *(const float4*)(g_B + (size_t)(base + r0 + r) * HIDF + l * 4);
        acc.x += v.x; acc.y += v.y; acc.z += v.z; acc.w += v.w;
    }
    if (curg >= 0) {
        float* sp = g_sums + curg * HIDF + l * 4;
        atomicAdd(sp + 0, acc.x); atomicAdd(sp + 1, acc.y);
        atomicAdd(sp + 2, acc.z); atomicAdd(sp + 3, acc.w);
    }
}

__global__ void fc_kernel(const float* __restrict__ Wfc, const float* __restrict__ bfc,
                          float* __restrict__ out) {
    int g = blockIdx.x, t = threadIdx.x;   // 128 threads
    float cnt = g_counts[g];
    cnt = (cnt > 1.0f) ? cnt : 1.0f;
    float v = g_sums[g * HIDF + t] * (1.0f / cnt) * Wfc[t];
#pragma unroll
    for (int o = 16; o; o >>= 1) v += __shfl_down_sync(0xffffffffu, v, o);
    __shared__ float sr[4];
    if ((t & 31) == 0) sr[t >> 5] = v;
    __syncthreads();
    if (t == 0) out[g] = sr[0] + sr[1] + sr[2] + sr[3] + bfc[0];
}

// ---------------- launch ----------------
extern "C" void kernel_launch(void* const* d_in, const int* in_sizes, int n_in,
                              void* d_out, int out_size) {
    const float* x   = (const float*)d_in[0];
    const int*   ei  = (const int*)  d_in[1];
    const float* ew  = (const float*)d_in[2];
    const int*   bat = (const int*)  d_in[3];
    const float* W1  = (const float*)d_in[4];
    const float* b1  = (const float*)d_in[5];
    const float* W2  = (const float*)d_in[6];
    const float* b2  = (const float*)d_in[7];
    const float* Wfc = (const float*)d_in[8];
    const float* bfc = (const float*)d_in[9];
    float* out = (float*)d_out;

    const int n  = in_sizes[3];   // nodes
    const int ne = in_sizes[2];   // edges
    const int* src = ei;
    const int* dst = ei + ne;

    // ---- preprocess: weighted degree, CSR sort by dst, coefs ----
    zero_meta_kernel<<<(n + 255) / 256, 256>>>(n);
    hist_kernel<<<(ne + 255) / 256, 256>>>(dst, ew, ne);
    dinv_kernel<<<(n + 255) / 256, 256>>>(n);
    scan_kernel<<<1, 1024>>>(n);
    scatter_kernel<<<(ne + 255) / 256, 256>>>(src, dst, ew, ne);

    const int gemm_blocks = (n + 63) / 64;
    const int agg_blocks  = (n + 7) / 8;      // warp per node, 8 warps/block

    // layer 1
    gemm128_kernel<<<gemm_blocks, 256>>>(x, W1, n, 0);
    agg_csr_kernel<<<agg_blocks, 256>>>(b1, n);

    // layer 2 (ELU fused into GEMM operand load)
    gemm128_kernel<<<gemm_blocks, 256>>>(x /*unused*/, W2, n, 1);
    agg_csr_kernel<<<agg_blocks, 256>>>(b2, n);

    // mean pool + FC
    zero_pool_kernel<<<(N_GRAPHS * HIDF + 255) / 256, 256>>>();
    pool_kernel<<<(n + 255) / 256, 256>>>(bat, n);
    fc_kernel<<<N_GRAPHS, HIDF>>>(Wfc, bfc, out);
}

// round 4
// speedup vs baseline: 3.1746x; 1.1466x over previous
#include <cuda_runtime.h>
#include <math.h>

#define N_NODES   200000
#define N_EDGES   6400000
#define HIDF      128
#define N_GRAPHS  64
#define SCAN_BLK  1024

typedef unsigned long long ull;

// ---------------- scratch (device globals; referenced from device code ONLY) ----
__device__ float g_dinv[N_NODES];                 // weighted deg -> rsqrt(deg)
__device__ int   g_cnt[N_NODES];                  // in-degree (edge count)
__device__ int   g_fill[N_NODES];                 // scatter cursor
__device__ int   g_rowptr[N_NODES + 1];           // CSR row pointers (by dst)
__device__ int   g_bsum[256];                     // scan block sums
__device__ int   g_boff[256];                     // scan block offsets
__device__ int2  g_edge[N_EDGES];                 // {src, coef bits} sorted by dst
__device__ float g_H[(size_t)N_NODES * HIDF];     // X@W
__device__ float g_B[(size_t)N_NODES * HIDF];     // layer output
__device__ float g_sums[N_GRAPHS * HIDF];
__device__ float g_counts[N_GRAPHS];

// ---------------- f32x2 packed-FMA helpers (sm_100+) ----------------
__device__ __forceinline__ ull fma2(ull a, ull b, ull c) {
    ull d;
    asm("fma.rn.f32x2 %0, %1, %2, %3;" : "=l"(d) : "l"(a), "l"(b), "l"(c));
    return d;
}
__device__ __forceinline__ ull pack2(float x) {
    ull d;
    asm("mov.b64 %0, {%1, %1};" : "=l"(d) : "f"(x));
    return d;
}

// ---------------- preprocess: degrees + counts ----------------
__global__ void zero_meta_kernel(int n) {
    int i = blockIdx.x * blockDim.x + threadIdx.x;
    if (i < n) {
        g_dinv[i] = 1.0f;   // self-loop weight seed
        g_cnt[i]  = 0;
        g_fill[i] = 0;
    }
}

__global__ void hist_kernel(const int* __restrict__ dst,
                            const float* __restrict__ ew, int ne) {
    int e = blockIdx.x * blockDim.x + threadIdx.x;
    if (e < ne) {
        int d = dst[e];
        atomicAdd(&g_dinv[d], ew[e]);
        atomicAdd(&g_cnt[d], 1);
    }
}

__global__ void dinv_kernel(int n) {
    int i = blockIdx.x * blockDim.x + threadIdx.x;
    if (i < n) {
        float d = g_dinv[i];
        g_dinv[i] = (d > 0.0f) ? rsqrtf(d) : 0.0f;
    }
}

// ---------------- hierarchical scan: g_cnt -> g_rowptr ----------------
// pass 1: per-block exclusive scan (1024 elements/block), block totals to g_bsum
__global__ void scan1_kernel(int n) {
    __shared__ int wsum[32];
    const int t = threadIdx.x;
    const int w = t >> 5, l = t & 31;
    const int i = blockIdx.x * SCAN_BLK + t;

    int orig = (i < n) ? g_cnt[i] : 0;
    int v = orig;
#pragma unroll
    for (int o = 1; o < 32; o <<= 1) {
        int u = __shfl_up_sync(0xffffffffu, v, o);
        if (l >= o) v += u;
    }
    if (l == 31) wsum[w] = v;
    __syncthreads();
    if (t < 32) {
        int s = wsum[t];
#pragma unroll
        for (int o = 1; o < 32; o <<= 1) {
            int u = __shfl_up_sync(0xffffffffu, s, o);
            if (t >= o) s += u;
        }
        wsum[t] = s;
    }
    __syncthreads();

    int excl = v - orig + ((w > 0) ? wsum[w - 1] : 0);
    if (i < n) g_rowptr[i] = excl;
    if (t == SCAN_BLK - 1) g_bsum[blockIdx.x] = excl + orig;
}

// pass 2: single block scans block sums (nb <= 256)
__global__ void scan2_kernel(int nb) {
    __shared__ int wsum[8];
    const int t = threadIdx.x;             // 256 threads
    const int w = t >> 5, l = t & 31;
    int orig = (t < nb) ? g_bsum[t] : 0;
    int v = orig;
#pragma unroll
    for (int o = 1; o < 32; o <<= 1) {
        int u = __shfl_up_sync(0xffffffffu, v, o);
        if (l >= o) v += u;
    }
    if (l == 31) wsum[w] = v;
    __syncthreads();
    if (t < 8) {
        int s = wsum[t];
#pragma unroll
        for (int o = 1; o < 8; o <<= 1) {
            int u = __shfl_up_sync(0xffu, s, o);
            if (t >= o) s += u;
        }
        wsum[t] = s;
    }
    __syncthreads();
    int excl = v - orig + ((w > 0) ? wsum[w - 1] : 0);
    if (t < nb) g_boff[t] = excl;
}

// pass 3: add block offsets; rowptr[n] = ne (every edge counted exactly once)
__global__ void scan3_kernel(int n, int ne) {
    int i = blockIdx.x * blockDim.x + threadIdx.x;
    if (i < n) g_rowptr[i] += g_boff[i >> 10];
    if (i == 0) g_rowptr[n] = ne;
}

// scatter edges into dst-sorted CSR, coef computed inline
__global__ void scatter_kernel(const int* __restrict__ src, const int* __restrict__ dst,
                               const float* __restrict__ ew, int ne) {
    int e = blockIdx.x * blockDim.x + threadIdx.x;
    if (e >= ne) return;
    int s = src[e], d = dst[e];
    float c = g_dinv[s] * ew[e] * g_dinv[d];
    int pos = g_rowptr[d] + atomicAdd(&g_fill[d], 1);
    g_edge[pos] = make_int2(s, __float_as_int(c));
}

// ---------------- SGEMM: g_H[n,128] = act(X[n,128]) @ W[128,128] ----------------
// f32x2 packed FMA; 256 threads = 8 warps; warp computes 8 rows; lane owns 4 cols
// (2 packed accumulators). x values stored pre-duplicated {x,x} in smem.
__global__ void gemm128_kernel(const float* __restrict__ Xext,
                               const float* __restrict__ W,
                               int n, int src_sel) {
    __shared__ float sW[32][HIDF];       // 16KB K-chunk of W
    __shared__ ull   sX2[8][8][32];      // 16KB per-warp packed x rows

    const float* X = src_sel ? (const float*)g_B : Xext;

    const int t = threadIdx.x;
    const int w = t >> 5, l = t & 31;
    const int row0 = (blockIdx.x * 8 + w) * 8;

    ull acc0[8], acc1[8];
#pragma unroll
    for (int r = 0; r < 8; ++r) { acc0[r] = 0ull; acc1[r] = 0ull; }

    for (int c = 0; c < 4; ++c) {
        const float4* Wv = (const float4*)(W + c * 32 * HIDF);
        float4* sWv = (float4*)&sW[0][0];
#pragma unroll
        for (int i = 0; i < 4; ++i) sWv[t + 256 * i] = Wv[t + 256 * i];
#pragma unroll
        for (int r = 0; r < 8; ++r) {
            int row = row0 + r;
            float v = 0.0f;
            if (row < n) v = X[(size_t)row * HIDF + c * 32 + l];
            if (src_sel) v = (v > 0.0f) ? v : expm1f(v);   // ELU
            sX2[w][r][l] = pack2(v);
        }
        __syncthreads();
#pragma unroll
        for (int k = 0; k < 32; ++k) {
            ulonglong2 wv = *(const ulonglong2*)&sW[k][l * 4];
#pragma unroll
            for (int r = 0; r < 8; ++r) {
                ull xv = sX2[w][r][k];
                acc0[r] = fma2(xv, wv.x, acc0[r]);
                acc1[r] = fma2(xv, wv.y, acc1[r]);
            }
        }
        __syncthreads();
    }
#pragma unroll
    for (int r = 0; r < 8; ++r) {
        int row = row0 + r;
        if (row < n)
            *(ulonglong2*)&g_H[(size_t)row * HIDF + l * 4] =
                make_ulonglong2(acc0[r], acc1[r]);
    }
}

// ---------------- CSR aggregation (atomic-free), self-loop + bias fused ---------
// one warp per dst node: B[d] = dinv[d]^2*H[d] + bias + sum_e coef*H[src]
__global__ void agg_csr_kernel(const float* __restrict__ bias, int n) {
    int node = (blockIdx.x * blockDim.x + threadIdx.x) >> 5;
    int l = threadIdx.x & 31;
    if (node >= n) return;

    int beg = g_rowptr[node];
    int end = g_rowptr[node + 1];

    float di = g_dinv[node];
    float s = di * di;
    float4 h = *(const float4*)(g_H + (size_t)node * HIDF + l * 4);
    float4 b = ((const float4*)bias)[l];
    float4 acc = make_float4(s * h.x + b.x, s * h.y + b.y,
                             s * h.z + b.z, s * h.w + b.w);

    for (int e = beg; e < end; ++e) {
        int2 ed = g_edge[e];
        float c = __int_as_float(ed.y);
        float4 hv = *(const float4*)(g_H + (size_t)ed.x * HIDF + l * 4);
        acc.x += c * hv.x;
        acc.y += c * hv.y;
        acc.z += c * hv.z;
        acc.w += c * hv.w;
    }
    *(float4*)(g_B + (size_t)node * HIDF + l * 4) = acc;
}

// ---------------- pooling ----------------
__global__ void zero_pool_kernel() {
    int t = blockIdx.x * blockDim.x + threadIdx.x;
    if (t < N_GRAPHS * HIDF) g_sums[t] = 0.0f;
    if (t < N_GRAPHS) g_counts[t] = 0.0f;
}

__global__ void pool_kernel(const int* __restrict__ batch, int n) {
    __shared__ int sb[256];
    __shared__ int scnt[N_GRAPHS];
    int t = threadIdx.x;
    int base = blockIdx.x * 256;
    if (t < N_GRAPHS) scnt[t] = 0;
    __syncthreads();
    int node = base + t;
    int g = -1;
    if (node < n) {
        g = batch[node];
        atomicAdd(&scnt[g], 1);
    }
    sb[t] = g;
    __syncthreads();
    if (t < N_GRAPHS && scnt[t] > 0) atomicAdd(&g_counts[t], (float)scnt[t]);

    int w = t >> 5, l = t & 31;
    int r0 = w * 32;
    float4 acc = make_float4(0.f, 0.f, 0.f, 0.f);
    int curg = -1;
    for (int r = 0; r < 32; ++r) {
        int gg = sb[r0 + r];
        if (gg < 0) break;
        if (gg != curg) {
            if (curg >= 0) {
                float* sp = g_sums + curg * HIDF + l * 4;
                atomicAdd(sp + 0, acc.x); atomicAdd(sp + 1, acc.y);
                atomicAdd(sp + 2, acc.z); atomicAdd(sp + 3, acc.w);
                acc = make_float4(0.f, 0.f, 0.f, 0.f);
            }
            curg = gg;
        }
        float4 v = *(const float4*)(g_B + (size_t)(base + r0 + r) * HIDF + l * 4);
        acc.x += v.x; acc.y += v.y; acc.z += v.z; acc.w += v.w;
    }
    if (curg >= 0) {
        float* sp = g_sums + curg * HIDF + l * 4;
        atomicAdd(sp + 0, acc.x); atomicAdd(sp + 1, acc.y);
        atomicAdd(sp + 2, acc.z); atomicAdd(sp + 3, acc.w);
    }
}

__global__ void fc_kernel(const float* __restrict__ Wfc, const float* __restrict__ bfc,
                          float* __restrict__ out) {
    int g = blockIdx.x, t = threadIdx.x;   // 128 threads
    float cnt = g_counts[g];
    cnt = (cnt > 1.0f) ? cnt : 1.0f;
    float v = g_sums[g * HIDF + t] * (1.0f / cnt) * Wfc[t];
#pragma unroll
    for (int o = 16; o; o >>= 1) v += __shfl_down_sync(0xffffffffu, v, o);
    __shared__ float sr[4];
    if ((t & 31) == 0) sr[t >> 5] = v;
    __syncthreads();
    if (t == 0) out[g] = sr[0] + sr[1] + sr[2] + sr[3] + bfc[0];
}

// ---------------- launch ----------------
extern "C" void kernel_launch(void* const* d_in, const int* in_sizes, int n_in,
                              void* d_out, int out_size) {
    const float* x   = (const float*)d_in[0];
    const int*   ei  = (const int*)  d_in[1];
    const float* ew  = (const float*)d_in[2];
    const int*   bat = (const int*)  d_in[3];
    const float* W1  = (const float*)d_in[4];
    const float* b1  = (const float*)d_in[5];
    const float* W2  = (const float*)d_in[6];
    const float* b2  = (const float*)d_in[7];
    const float* Wfc = (const float*)d_in[8];
    const float* bfc = (const float*)d_in[9];
    float* out = (float*)d_out;

    const int n  = in_sizes[3];   // nodes
    const int ne = in_sizes[2];   // edges
    const int* src = ei;
    const int* dst = ei + ne;

    // ---- preprocess: weighted degree, CSR sort by dst, coefs ----
    zero_meta_kernel<<<(n + 255) / 256, 256>>>(n);
    hist_kernel<<<(ne + 255) / 256, 256>>>(dst, ew, ne);
    dinv_kernel<<<(n + 255) / 256, 256>>>(n);
    const int nb = (n + SCAN_BLK - 1) / SCAN_BLK;
    scan1_kernel<<<nb, SCAN_BLK>>>(n);
    scan2_kernel<<<1, 256>>>(nb);
    scan3_kernel<<<(n + 255) / 256, 256>>>(n, ne);
    scatter_kernel<<<(ne + 255) / 256, 256>>>(src, dst, ew, ne);

    const int gemm_blocks = (n + 63) / 64;
    const int agg_blocks  = (n + 7) / 8;      // warp per node, 8 warps/block

    // layer 1
    gemm128_kernel<<<gemm_blocks, 256>>>(x, W1, n, 0);
    agg_csr_kernel<<<agg_blocks, 256>>>(b1, n);

    // layer 2 (ELU fused into GEMM operand load)
    gemm128_kernel<<<gemm_blocks, 256>>>(x /*unused*/, W2, n, 1);
    agg_csr_kernel<<<agg_blocks, 256>>>(b2, n);

    // mean pool + FC
    zero_pool_kernel<<<(N_GRAPHS * HIDF + 255) / 256, 256>>>();
    pool_kernel<<<(n + 255) / 256, 256>>>(bat, n);
    fc_kernel<<<N_GRAPHS, HIDF>>>(Wfc, bfc, out);
}

// round 5
// speedup vs baseline: 3.6471x; 1.1488x over previous
#include <cuda_runtime.h>
#include <cuda_fp16.h>
#include <math.h>

#define N_NODES   200000
#define N_EDGES   6400000
#define HIDF      128
#define N_GRAPHS  64
#define SCAN_BLK  1024

typedef unsigned long long ull;

// ---------------- scratch (device globals; referenced from device code ONLY) ----
__device__ float  g_dinv[N_NODES];                 // weighted deg -> rsqrt(deg)
__device__ int    g_cnt[N_NODES];                  // in-degree (edge count)
__device__ int    g_fill[N_NODES];                 // scatter cursor
__device__ int    g_rowptr[N_NODES + 1];           // CSR row pointers (by dst)
__device__ int    g_bsum[256];                     // scan block sums
__device__ int    g_boff[256];                     // scan block offsets
__device__ int2   g_edge[N_EDGES];                 // {src, coef bits} sorted by dst
__device__ __half g_Hh[(size_t)N_NODES * HIDF];    // X@W in fp16 (gather matrix)
__device__ float  g_B[(size_t)N_NODES * HIDF];     // layer output (fp32)
__device__ float  g_sums[N_GRAPHS * HIDF];
__device__ float  g_counts[N_GRAPHS];

// ---------------- f32x2 packed-FMA helpers (sm_100+) ----------------
__device__ __forceinline__ ull fma2(ull a, ull b, ull c) {
    ull d;
    asm("fma.rn.f32x2 %0, %1, %2, %3;" : "=l"(d) : "l"(a), "l"(b), "l"(c));
    return d;
}
__device__ __forceinline__ ull pack2(float x) {
    ull d;
    asm("mov.b64 %0, {%1, %1};" : "=l"(d) : "f"(x));
    return d;
}

// ---------------- preprocess: degrees + counts ----------------
__global__ void zero_meta_kernel(int n) {
    int i = blockIdx.x * blockDim.x + threadIdx.x;
    if (i < n) {
        g_dinv[i] = 1.0f;   // self-loop weight seed
        g_cnt[i]  = 0;
        g_fill[i] = 0;
    }
}

// 4 edges per thread, vectorized loads
__global__ void hist_kernel(const int* __restrict__ dst,
                            const float* __restrict__ ew, int ne) {
    int q = blockIdx.x * blockDim.x + threadIdx.x;   // quad index
    int e0 = q * 4;
    if (e0 + 3 < ne) {
        int4   d4 = *(const int4*)(dst + e0);
        float4 w4 = *(const float4*)(ew + e0);
        atomicAdd(&g_dinv[d4.x], w4.x); atomicAdd(&g_cnt[d4.x], 1);
        atomicAdd(&g_dinv[d4.y], w4.y); atomicAdd(&g_cnt[d4.y], 1);
        atomicAdd(&g_dinv[d4.z], w4.z); atomicAdd(&g_cnt[d4.z], 1);
        atomicAdd(&g_dinv[d4.w], w4.w); atomicAdd(&g_cnt[d4.w], 1);
    } else {
        for (int e = e0; e < ne; ++e) {
            int d = dst[e];
            atomicAdd(&g_dinv[d], ew[e]);
            atomicAdd(&g_cnt[d], 1);
        }
    }
}

__global__ void dinv_kernel(int n) {
    int i = blockIdx.x * blockDim.x + threadIdx.x;
    if (i < n) {
        float d = g_dinv[i];
        g_dinv[i] = (d > 0.0f) ? rsqrtf(d) : 0.0f;
    }
}

// ---------------- hierarchical scan: g_cnt -> g_rowptr ----------------
__global__ void scan1_kernel(int n) {
    __shared__ int wsum[32];
    const int t = threadIdx.x;
    const int w = t >> 5, l = t & 31;
    const int i = blockIdx.x * SCAN_BLK + t;

    int orig = (i < n) ? g_cnt[i] : 0;
    int v = orig;
#pragma unroll
    for (int o = 1; o < 32; o <<= 1) {
        int u = __shfl_up_sync(0xffffffffu, v, o);
        if (l >= o) v += u;
    }
    if (l == 31) wsum[w] = v;
    __syncthreads();
    if (t < 32) {
        int s = wsum[t];
#pragma unroll
        for (int o = 1; o < 32; o <<= 1) {
            int u = __shfl_up_sync(0xffffffffu, s, o);
            if (t >= o) s += u;
        }
        wsum[t] = s;
    }
    __syncthreads();

    int excl = v - orig + ((w > 0) ? wsum[w - 1] : 0);
    if (i < n) g_rowptr[i] = excl;
    if (t == SCAN_BLK - 1) g_bsum[blockIdx.x] = excl + orig;
}

__global__ void scan2_kernel(int nb) {
    __shared__ int wsum[8];
    const int t = threadIdx.x;             // 256 threads
    const int w = t >> 5, l = t & 31;
    int orig = (t < nb) ? g_bsum[t] : 0;
    int v = orig;
#pragma unroll
    for (int o = 1; o < 32; o <<= 1) {
        int u = __shfl_up_sync(0xffffffffu, v, o);
        if (l >= o) v += u;
    }
    if (l == 31) wsum[w] = v;
    __syncthreads();
    if (t < 8) {
        int s = wsum[t];
#pragma unroll
        for (int o = 1; o < 8; o <<= 1) {
            int u = __shfl_up_sync(0xffu, s, o);
            if (t >= o) s += u;
        }
        wsum[t] = s;
    }
    __syncthreads();
    int excl = v - orig + ((w > 0) ? wsum[w - 1] : 0);
    if (t < nb) g_boff[t] = excl;
}

__global__ void scan3_kernel(int n, int ne) {
    int i = blockIdx.x * blockDim.x + threadIdx.x;
    if (i < n) g_rowptr[i] += g_boff[i >> 10];
    if (i == 0) g_rowptr[n] = ne;
}

// scatter edges into dst-sorted CSR, coef computed inline
__global__ void scatter_kernel(const int* __restrict__ src, const int* __restrict__ dst,
                               const float* __restrict__ ew, int ne) {
    int e = blockIdx.x * blockDim.x + threadIdx.x;
    if (e >= ne) return;
    int s = src[e], d = dst[e];
    float c = g_dinv[s] * ew[e] * g_dinv[d];
    int pos = g_rowptr[d] + atomicAdd(&g_fill[d], 1);
    g_edge[pos] = make_int2(s, __float_as_int(c));
}

// ---------------- SGEMM: g_Hh[n,128] = fp16( act(X[n,128]) @ W[128,128] ) --------
// f32x2 packed FMA, fp32 accumulation; output stored fp16 for the gather phase.
// 256 threads = 8 warps; warp computes 8 rows; lane owns 4 output cols.
__global__ void gemm128_kernel(const float* __restrict__ Xext,
                               const float* __restrict__ W,
                               int n, int src_sel) {
    __shared__ float sW[32][HIDF];       // 16KB K-chunk of W
    __shared__ ull   sX2[8][8][32];      // 16KB per-warp packed x rows

    const float* X = src_sel ? (const float*)g_B : Xext;

    const int t = threadIdx.x;
    const int w = t >> 5, l = t & 31;
    const int row0 = (blockIdx.x * 8 + w) * 8;

    ull acc0[8], acc1[8];
#pragma unroll
    for (int r = 0; r < 8; ++r) { acc0[r] = 0ull; acc1[r] = 0ull; }

    for (int c = 0; c < 4; ++c) {
        const float4* Wv = (const float4*)(W + c * 32 * HIDF);
        float4* sWv = (float4*)&sW[0][0];
#pragma unroll
        for (int i = 0; i < 4; ++i) sWv[t + 256 * i] = Wv[t + 256 * i];
#pragma unroll
        for (int r = 0; r < 8; ++r) {
            int row = row0 + r;
            float v = 0.0f;
            if (row < n) v = X[(size_t)row * HIDF + c * 32 + l];
            if (src_sel) v = (v > 0.0f) ? v : expm1f(v);   // ELU
            sX2[w][r][l] = pack2(v);
        }
        __syncthreads();
#pragma unroll
        for (int k = 0; k < 32; ++k) {
            ulonglong2 wv = *(const ulonglong2*)&sW[k][l * 4];
#pragma unroll
            for (int r = 0; r < 8; ++r) {
                ull xv = sX2[w][r][k];
                acc0[r] = fma2(xv, wv.x, acc0[r]);
                acc1[r] = fma2(xv, wv.y, acc1[r]);
            }
        }
        __syncthreads();
    }
#pragma unroll
    for (int r = 0; r < 8; ++r) {
        int row = row0 + r;
        if (row < n) {
            float2 f0 = *(float2*)&acc0[r];
            float2 f1 = *(float2*)&acc1[r];
            __half2 h0 = __floats2half2_rn(f0.x, f0.y);
            __half2 h1 = __floats2half2_rn(f1.x, f1.y);
            uint2 pk = make_uint2(*(unsigned*)&h0, *(unsigned*)&h1);
            *(uint2*)(g_Hh + (size_t)row * HIDF + l * 4) = pk;
        }
    }
}

// ---------------- CSR aggregation (atomic-free), self-loop + bias fused ---------
// one warp per dst node: B[d] = dinv[d]^2*Hh[d] + bias + sum_e coef*Hh[src]
// fp16 gathers (256B/edge), fp32 accumulation.
__global__ void agg_csr_kernel(const float* __restrict__ bias, int n) {
    int node = (blockIdx.x * blockDim.x + threadIdx.x) >> 5;
    int l = threadIdx.x & 31;
    if (node >= n) return;

    int beg = g_rowptr[node];
    int end = g_rowptr[node + 1];

    float di = g_dinv[node];
    float s = di * di;
    uint2 hu = *(const uint2*)(g_Hh + (size_t)node * HIDF + l * 4);
    float2 h0 = __half22float2(*(__half2*)&hu.x);
    float2 h1 = __half22float2(*(__half2*)&hu.y);
    float4 b = ((const float4*)bias)[l];
    float4 acc = make_float4(s * h0.x + b.x, s * h0.y + b.y,
                             s * h1.x + b.z, s * h1.y + b.w);

    for (int e = beg; e < end; ++e) {
        int2 ed = g_edge[e];
        float c = __int_as_float(ed.y);
        uint2 gu = *(const uint2*)(g_Hh + (size_t)ed.x * HIDF + l * 4);
        float2 g0 = __half22float2(*(__half2*)&gu.x);
        float2 g1 = __half22float2(*(__half2*)&gu.y);
        acc.x += c * g0.x;
        acc.y += c * g0.y;
        acc.z += c * g1.x;
        acc.w += c * g1.y;
    }
    *(float4*)(g_B + (size_t)node * HIDF + l * 4) = acc;
}

// ---------------- pooling ----------------
__global__ void zero_pool_kernel() {
    int t = blockIdx.x * blockDim.x + threadIdx.x;
    if (t < N_GRAPHS * HIDF) g_sums[t] = 0.0f;
    if (t < N_GRAPHS) g_counts[t] = 0.0f;
}

__global__ void pool_kernel(const int* __restrict__ batch, int n) {
    __shared__ int sb[256];
    __shared__ int scnt[N_GRAPHS];
    int t = threadIdx.x;
    int base = blockIdx.x * 256;
    if (t < N_GRAPHS) scnt[t] = 0;
    __syncthreads();
    int node = base + t;
    int g = -1;
    if (node < n) {
        g = batch[node];
        atomicAdd(&scnt[g], 1);
    }
    sb[t] = g;
    __syncthreads();
    if (t < N_GRAPHS && scnt[t] > 0) atomicAdd(&g_counts[t], (float)scnt[t]);

    int w = t >> 5, l = t & 31;
    int r0 = w * 32;
    float4 acc = make_float4(0.f, 0.f, 0.f, 0.f);
    int curg = -1;
    for (int r = 0; r < 32; ++r) {
        int gg = sb[r0 + r];
        if (gg < 0) break;
        if (gg != curg) {
            if (curg >= 0) {
                float* sp = g_sums + curg * HIDF + l * 4;
                atomicAdd(sp + 0, acc.x); atomicAdd(sp + 1, acc.y);
                atomicAdd(sp + 2, acc.z); atomicAdd(sp + 3, acc.w);
                acc = make_float4(0.f, 0.f, 0.f, 0.f);
            }
            curg = gg;
        }
        float4 v = *(const float4*)(g_B + (size_t)(base + r0 + r) * HIDF + l * 4);
        acc.x += v.x; acc.y += v.y; acc.z += v.z; acc.w += v.w;
    }
    if (curg >= 0) {
        float* sp = g_sums + curg * HIDF + l * 4;
        atomicAdd(sp + 0, acc.x); atomicAdd(sp + 1, acc.y);
        atomicAdd(sp + 2, acc.z); atomicAdd(sp + 3, acc.w);
    }
}

__global__ void fc_kernel(const float* __restrict__ Wfc, const float* __restrict__ bfc,
                          float* __restrict__ out) {
    int g = blockIdx.x, t = threadIdx.x;   // 128 threads
    float cnt = g_counts[g];
    cnt = (cnt > 1.0f) ? cnt : 1.0f;
    float v = g_sums[g * HIDF + t] * (1.0f / cnt) * Wfc[t];
#pragma unroll
    for (int o = 16; o; o >>= 1) v += __shfl_down_sync(0xffffffffu, v, o);
    __shared__ float sr[4];
    if ((t & 31) == 0) sr[t >> 5] = v;
    __syncthreads();
    if (t == 0) out[g] = sr[0] + sr[1] + sr[2] + sr[3] + bfc[0];
}

// ---------------- launch ----------------
extern "C" void kernel_launch(void* const* d_in, const int* in_sizes, int n_in,
                              void* d_out, int out_size) {
    const float* x   = (const float*)d_in[0];
    const int*   ei  = (const int*)  d_in[1];
    const float* ew  = (const float*)d_in[2];
    const int*   bat = (const int*)  d_in[3];
    const float* W1  = (const float*)d_in[4];
    const float* b1  = (const float*)d_in[5];
    const float* W2  = (const float*)d_in[6];
    const float* b2  = (const float*)d_in[7];
    const float* Wfc = (const float*)d_in[8];
    const float* bfc = (const float*)d_in[9];
    float* out = (float*)d_out;

    const int n  = in_sizes[3];   // nodes
    const int ne = in_sizes[2];   // edges
    const int* src = ei;
    const int* dst = ei + ne;

    // ---- preprocess: weighted degree, CSR sort by dst, coefs ----
    zero_meta_kernel<<<(n + 255) / 256, 256>>>(n);
    hist_kernel<<<((ne + 3) / 4 + 255) / 256, 256>>>(dst, ew, ne);
    dinv_kernel<<<(n + 255) / 256, 256>>>(n);
    const int nb = (n + SCAN_BLK - 1) / SCAN_BLK;
    scan1_kernel<<<nb, SCAN_BLK>>>(n);
    scan2_kernel<<<1, 256>>>(nb);
    scan3_kernel<<<(n + 255) / 256, 256>>>(n, ne);
    scatter_kernel<<<(ne + 255) / 256, 256>>>(src, dst, ew, ne);

    const int gemm_blocks = (n + 63) / 64;
    const int agg_blocks  = (n + 7) / 8;      // warp per node, 8 warps/block

    // layer 1
    gemm128_kernel<<<gemm_blocks, 256>>>(x, W1, n, 0);
    agg_csr_kernel<<<agg_blocks, 256>>>(b1, n);

    // layer 2 (ELU fused into GEMM operand load)
    gemm128_kernel<<<gemm_blocks, 256>>>(x /*unused*/, W2, n, 1);
    agg_csr_kernel<<<agg_blocks, 256>>>(b2, n);

    // mean pool + FC
    zero_pool_kernel<<<(N_GRAPHS * HIDF + 255) / 256, 256>>>();
    pool_kernel<<<(n + 255) / 256, 256>>>(bat, n);
    fc_kernel<<<N_GRAPHS, HIDF>>>(Wfc, bfc, out);
}

// round 6
// speedup vs baseline: 5.8754x; 1.6110x over previous
#include <cuda_runtime.h>
#include <cuda_fp16.h>
#include <math.h>

#define N_NODES   200000
#define N_EDGES   6400000
#define HIDF      128
#define N_GRAPHS  64
#define SCAN_BLK  1024

typedef unsigned long long ull;
typedef unsigned int uint;

// ---------------- scratch (device globals; referenced from device code ONLY) ----
__device__ float  g_dinv[N_NODES];                 // weighted deg -> rsqrt(deg)
__device__ int    g_cnt[N_NODES];                  // in-degree (edge count)
__device__ int    g_fill[N_NODES];                 // scatter cursor
__device__ int    g_rowptr[N_NODES + 1];           // CSR row pointers (by dst)
__device__ int    g_bsum[256];                     // scan block sums
__device__ int    g_boff[256];                     // scan block offsets
__device__ int2   g_edge[N_EDGES];                 // {src, coef bits} sorted by dst
__device__ __half g_Hh[(size_t)N_NODES * HIDF];    // X@W in fp16 (gather matrix)
__device__ float  g_B[(size_t)N_NODES * HIDF];     // layer output (fp32)
__device__ float  g_sums[N_GRAPHS * HIDF];
__device__ float  g_counts[N_GRAPHS];

// ---------------- preprocess: degrees + counts ----------------
__global__ void zero_meta_kernel(int n) {
    int i = blockIdx.x * blockDim.x + threadIdx.x;
    if (i < n) {
        g_dinv[i] = 1.0f;   // self-loop weight seed
        g_cnt[i]  = 0;
        g_fill[i] = 0;
    }
}

// 4 edges per thread, vectorized loads
__global__ void hist_kernel(const int* __restrict__ dst,
                            const float* __restrict__ ew, int ne) {
    int q = blockIdx.x * blockDim.x + threadIdx.x;   // quad index
    int e0 = q * 4;
    if (e0 + 3 < ne) {
        int4   d4 = *(const int4*)(dst + e0);
        float4 w4 = *(const float4*)(ew + e0);
        atomicAdd(&g_dinv[d4.x], w4.x); atomicAdd(&g_cnt[d4.x], 1);
        atomicAdd(&g_dinv[d4.y], w4.y); atomicAdd(&g_cnt[d4.y], 1);
        atomicAdd(&g_dinv[d4.z], w4.z); atomicAdd(&g_cnt[d4.z], 1);
        atomicAdd(&g_dinv[d4.w], w4.w); atomicAdd(&g_cnt[d4.w], 1);
    } else {
        for (int e = e0; e < ne; ++e) {
            int d = dst[e];
            atomicAdd(&g_dinv[d], ew[e]);
            atomicAdd(&g_cnt[d], 1);
        }
    }
}

__global__ void dinv_kernel(int n) {
    int i = blockIdx.x * blockDim.x + threadIdx.x;
    if (i < n) {
        float d = g_dinv[i];
        g_dinv[i] = (d > 0.0f) ? rsqrtf(d) : 0.0f;
    }
}

// ---------------- hierarchical scan: g_cnt -> g_rowptr ----------------
__global__ void scan1_kernel(int n) {
    __shared__ int wsum[32];
    const int t = threadIdx.x;
    const int w = t >> 5, l = t & 31;
    const int i = blockIdx.x * SCAN_BLK + t;

    int orig = (i < n) ? g_cnt[i] : 0;
    int v = orig;
#pragma unroll
    for (int o = 1; o < 32; o <<= 1) {
        int u = __shfl_up_sync(0xffffffffu, v, o);
        if (l >= o) v += u;
    }
    if (l == 31) wsum[w] = v;
    __syncthreads();
    if (t < 32) {
        int s = wsum[t];
#pragma unroll
        for (int o = 1; o < 32; o <<= 1) {
            int u = __shfl_up_sync(0xffffffffu, s, o);
            if (t >= o) s += u;
        }
        wsum[t] = s;
    }
    __syncthreads();

    int excl = v - orig + ((w > 0) ? wsum[w - 1] : 0);
    if (i < n) g_rowptr[i] = excl;
    if (t == SCAN_BLK - 1) g_bsum[blockIdx.x] = excl + orig;
}

__global__ void scan2_kernel(int nb) {
    __shared__ int wsum[8];
    const int t = threadIdx.x;             // 256 threads
    const int w = t >> 5, l = t & 31;
    int orig = (t < nb) ? g_bsum[t] : 0;
    int v = orig;
#pragma unroll
    for (int o = 1; o < 32; o <<= 1) {
        int u = __shfl_up_sync(0xffffffffu, v, o);
        if (l >= o) v += u;
    }
    if (l == 31) wsum[w] = v;
    __syncthreads();
    if (t < 8) {
        int s = wsum[t];
#pragma unroll
        for (int o = 1; o < 8; o <<= 1) {
            int u = __shfl_up_sync(0xffu, s, o);
            if (t >= o) s += u;
        }
        wsum[t] = s;
    }
    __syncthreads();
    int excl = v - orig + ((w > 0) ? wsum[w - 1] : 0);
    if (t < nb) g_boff[t] = excl;
}

__global__ void scan3_kernel(int n, int ne) {
    int i = blockIdx.x * blockDim.x + threadIdx.x;
    if (i < n) g_rowptr[i] += g_boff[i >> 10];
    if (i == 0) g_rowptr[n] = ne;
}

// scatter edges into dst-sorted CSR, coef computed inline
__global__ void scatter_kernel(const int* __restrict__ src, const int* __restrict__ dst,
                               const float* __restrict__ ew, int ne) {
    int e = blockIdx.x * blockDim.x + threadIdx.x;
    if (e >= ne) return;
    int s = src[e], d = dst[e];
    float c = g_dinv[s] * ew[e] * g_dinv[d];
    int pos = g_rowptr[d] + atomicAdd(&g_fill[d], 1);
    g_edge[pos] = make_int2(s, __float_as_int(c));
}

// ---------------- tensor-core GEMM: g_Hh = fp16( act(X) @ W ) ----------------
// mma.sync m16n8k16, fp16 inputs / fp32 accum. 256 thr = 8 warps; warp does 16
// rows x 128 cols. A frags loaded straight from global fp32 (ELU+cvt fused);
// W transposed to fp16 smem once per block.
__device__ __forceinline__ uint cvt2h(float a, float b, int elu) {
    if (elu) {
        a = (a > 0.0f) ? a : expm1f(a);
        b = (b > 0.0f) ? b : expm1f(b);
    }
    __half2 h = __floats2half2_rn(a, b);
    return *(uint*)&h;
}

__global__ void __launch_bounds__(256)
gemm128_tc_kernel(const float* __restrict__ Xext, const float* __restrict__ W,
                  int n, int src_sel) {
    __shared__ __half sWt[128][132];   // transposed W, fp16, padded (33KB)

    const float* X = src_sel ? (const float*)g_B : Xext;
    const int t = threadIdx.x;
    const int w = t >> 5, l = t & 31;

    // stage W transposed: sWt[n][k] = W[k][n]
    for (int idx = t; idx < 128 * 128; idx += 256) {
        int k = idx >> 7, nn = idx & 127;
        sWt[nn][k] = __float2half(W[idx]);
    }
    __syncthreads();

    const int row_lo = blockIdx.x * 128 + w * 16 + (l >> 2);
    const int row_hi = row_lo + 8;
    const bool ok_lo = row_lo < n;
    const bool ok_hi = row_hi < n;
    const int kq = (l & 3) * 2;        // lane k-pair offset within k16

    float d[16][4];
#pragma unroll
    for (int nt = 0; nt < 16; ++nt)
#pragma unroll
        for (int j = 0; j < 4; ++j) d[nt][j] = 0.0f;

    const float* xlo = X + (size_t)row_lo * HIDF;
    const float* xhi = X + (size_t)row_hi * HIDF;

#pragma unroll
    for (int kt = 0; kt < 8; ++kt) {
        const int k0 = kt * 16 + kq;
        float2 x00 = ok_lo ? *(const float2*)(xlo + k0)     : make_float2(0.f, 0.f);
        float2 x01 = ok_lo ? *(const float2*)(xlo + k0 + 8) : make_float2(0.f, 0.f);
        float2 x10 = ok_hi ? *(const float2*)(xhi + k0)     : make_float2(0.f, 0.f);
        float2 x11 = ok_hi ? *(const float2*)(xhi + k0 + 8) : make_float2(0.f, 0.f);
        uint a0 = cvt2h(x00.x, x00.y, src_sel);
        uint a1 = cvt2h(x10.x, x10.y, src_sel);
        uint a2 = cvt2h(x01.x, x01.y, src_sel);
        uint a3 = cvt2h(x11.x, x11.y, src_sel);

#pragma unroll
        for (int nt = 0; nt < 16; ++nt) {
            int nn = nt * 8 + (l >> 2);
            uint b0 = *(const uint*)&sWt[nn][kt * 16 + kq];
            uint b1 = *(const uint*)&sWt[nn][kt * 16 + kq + 8];
            asm volatile(
                "mma.sync.aligned.m16n8k16.row.col.f32.f16.f16.f32 "
                "{%0,%1,%2,%3}, {%4,%5,%6,%7}, {%8,%9}, {%0,%1,%2,%3};"
                : "+f"(d[nt][0]), "+f"(d[nt][1]), "+f"(d[nt][2]), "+f"(d[nt][3])
                : "r"(a0), "r"(a1), "r"(a2), "r"(a3), "r"(b0), "r"(b1));
        }
    }

    // epilogue: D row = lane/4 (+8), cols = nt*8 + (lane%4)*2 + {0,1}; store fp16
#pragma unroll
    for (int nt = 0; nt < 16; ++nt) {
        int cn = nt * 8 + (l & 3) * 2;
        if (ok_lo) {
            __half2 h = __floats2half2_rn(d[nt][0], d[nt][1]);
            *(uint*)(g_Hh + (size_t)row_lo * HIDF + cn) = *(uint*)&h;
        }
        if (ok_hi) {
            __half2 h = __floats2half2_rn(d[nt][2], d[nt][3]);
            *(uint*)(g_Hh + (size_t)row_hi * HIDF + cn) = *(uint*)&h;
        }
    }
}

// ---------------- CSR aggregation (atomic-free), self-loop + bias fused ---------
__global__ void agg_csr_kernel(const float* __restrict__ bias, int n) {
    int node = (blockIdx.x * blockDim.x + threadIdx.x) >> 5;
    int l = threadIdx.x & 31;
    if (node >= n) return;

    int beg = g_rowptr[node];
    int end = g_rowptr[node + 1];

    float di = g_dinv[node];
    float s = di * di;
    uint2 hu = *(const uint2*)(g_Hh + (size_t)node * HIDF + l * 4);
    float2 h0 = __half22float2(*(__half2*)&hu.x);
    float2 h1 = __half22float2(*(__half2*)&hu.y);
    float4 b = ((const float4*)bias)[l];
    float4 acc = make_float4(s * h0.x + b.x, s * h0.y + b.y,
                             s * h1.x + b.z, s * h1.y + b.w);

    for (int e = beg; e < end; ++e) {
        int2 ed = g_edge[e];
        float c = __int_as_float(ed.y);
        uint2 gu = *(const uint2*)(g_Hh + (size_t)ed.x * HIDF + l * 4);
        float2 g0 = __half22float2(*(__half2*)&gu.x);
        float2 g1 = __half22float2(*(__half2*)&gu.y);
        acc.x += c * g0.x;
        acc.y += c * g0.y;
        acc.z += c * g1.x;
        acc.w += c * g1.y;
    }
    *(float4*)(g_B + (size_t)node * HIDF + l * 4) = acc;
}

// ---------------- pooling ----------------
__global__ void zero_pool_kernel() {
    int t = blockIdx.x * blockDim.x + threadIdx.x;
    if (t < N_GRAPHS * HIDF) g_sums[t] = 0.0f;
    if (t < N_GRAPHS) g_counts[t] = 0.0f;
}

__global__ void pool_kernel(const int* __restrict__ batch, int n) {
    __shared__ int sb[256];
    __shared__ int scnt[N_GRAPHS];
    int t = threadIdx.x;
    int base = blockIdx.x * 256;
    if (t < N_GRAPHS) scnt[t] = 0;
    __syncthreads();
    int node = base + t;
    int g = -1;
    if (node < n) {
        g = batch[node];
        atomicAdd(&scnt[g], 1);
    }
    sb[t] = g;
    __syncthreads();
    if (t < N_GRAPHS && scnt[t] > 0) atomicAdd(&g_counts[t], (float)scnt[t]);

    int w = t >> 5, l = t & 31;
    int r0 = w * 32;
    float4 acc = make_float4(0.f, 0.f, 0.f, 0.f);
    int curg = -1;
    for (int r = 0; r < 32; ++r) {
        int gg = sb[r0 + r];
        if (gg < 0) break;
        if (gg != curg) {
            if (curg >= 0) {
                float* sp = g_sums + curg * HIDF + l * 4;
                atomicAdd(sp + 0, acc.x); atomicAdd(sp + 1, acc.y);
                atomicAdd(sp + 2, acc.z); atomicAdd(sp + 3, acc.w);
                acc = make_float4(0.f, 0.f, 0.f, 0.f);
            }
            curg = gg;
        }
        float4 v = *(const float4*)(g_B + (size_t)(base + r0 + r) * HIDF + l * 4);
        acc.x += v.x; acc.y += v.y; acc.z += v.z; acc.w += v.w;
    }
    if (curg >= 0) {
        float* sp = g_sums + curg * HIDF + l * 4;
        atomicAdd(sp + 0, acc.x); atomicAdd(sp + 1, acc.y);
        atomicAdd(sp + 2, acc.z); atomicAdd(sp + 3, acc.w);
    }
}

__global__ void fc_kernel(const float* __restrict__ Wfc, const float* __restrict__ bfc,
                          float* __restrict__ out) {
    int g = blockIdx.x, t = threadIdx.x;   // 128 threads
    float cnt = g_counts[g];
    cnt = (cnt > 1.0f) ? cnt : 1.0f;
    float v = g_sums[g * HIDF + t] * (1.0f / cnt) * Wfc[t];
#pragma unroll
    for (int o = 16; o; o >>= 1) v += __shfl_down_sync(0xffffffffu, v, o);
    __shared__ float sr[4];
    if ((t & 31) == 0) sr[t >> 5] = v;
    __syncthreads();
    if (t == 0) out[g] = sr[0] + sr[1] + sr[2] + sr[3] + bfc[0];
}

// ---------------- launch ----------------
extern "C" void kernel_launch(void* const* d_in, const int* in_sizes, int n_in,
                              void* d_out, int out_size) {
    const float* x   = (const float*)d_in[0];
    const int*   ei  = (const int*)  d_in[1];
    const float* ew  = (const float*)d_in[2];
    const int*   bat = (const int*)  d_in[3];
    const float* W1  = (const float*)d_in[4];
    const float* b1  = (const float*)d_in[5];
    const float* W2  = (const float*)d_in[6];
    const float* b2  = (const float*)d_in[7];
    const float* Wfc = (const float*)d_in[8];
    const float* bfc = (const float*)d_in[9];
    float* out = (float*)d_out;

    const int n  = in_sizes[3];   // nodes
    const int ne = in_sizes[2];   // edges
    const int* src = ei;
    const int* dst = ei + ne;

    // ---- preprocess: weighted degree, CSR sort by dst, coefs ----
    zero_meta_kernel<<<(n + 255) / 256, 256>>>(n);
    hist_kernel<<<((ne + 3) / 4 + 255) / 256, 256>>>(dst, ew, ne);
    dinv_kernel<<<(n + 255) / 256, 256>>>(n);
    const int nb = (n + SCAN_BLK - 1) / SCAN_BLK;
    scan1_kernel<<<nb, SCAN_BLK>>>(n);
    scan2_kernel<<<1, 256>>>(nb);
    scan3_kernel<<<(n + 255) / 256, 256>>>(n, ne);
    scatter_kernel<<<(ne + 255) / 256, 256>>>(src, dst, ew, ne);

    const int gemm_blocks = (n + 127) / 128;
    const int agg_blocks  = (n + 7) / 8;      // warp per node, 8 warps/block

    // layer 1
    gemm128_tc_kernel<<<gemm_blocks, 256>>>(x, W1, n, 0);
    agg_csr_kernel<<<agg_blocks, 256>>>(b1, n);

    // layer 2 (ELU fused into GEMM operand load)
    gemm128_tc_kernel<<<gemm_blocks, 256>>>(x /*unused*/, W2, n, 1);
    agg_csr_kernel<<<agg_blocks, 256>>>(b2, n);

    // mean pool + FC
    zero_pool_kernel<<<(N_GRAPHS * HIDF + 255) / 256, 256>>>();
    pool_kernel<<<(n + 255) / 256, 256>>>(bat, n);
    fc_kernel<<<N_GRAPHS, HIDF>>>(Wfc, bfc, out);
}